// round 5
// baseline (speedup 1.0000x reference)
#include <cuda_runtime.h>
#include <cuda_fp16.h>
#include <cstdint>
#include <math.h>

#define TOKENS 8192
#define DDIM   1024
#define HDIM   4096
#define NEXP   8
#define TOTROWS (2*TOKENS)

// ---------------- device scratch ---------------------------------------------
__device__ __half g_x16[(size_t)TOKENS * DDIM];
__device__ __half g_w1h[(size_t)NEXP * DDIM * HDIM];     // W1 fp16 [E,K,N]
__device__ __half g_w2h[(size_t)NEXP * HDIM * DDIM];     // W2 fp16 [E,K,N]
__device__ __half g_h[(size_t)(TOTROWS + 128) * HDIM];
__device__ float  g_y[(size_t)TOTROWS * DDIM];
__device__ int    g_cnt[NEXP];
__device__ int    g_off[NEXP];
__device__ int    g_idx[NEXP][TOKENS];
__device__ int    g_tok_e[TOKENS][2];
__device__ int    g_tok_p[TOKENS][2];
__device__ float  g_tok_g[TOKENS][2];

// ---------------- helpers ----------------------------------------------------
__device__ __forceinline__ uint32_t s2u(const void* p) {
    return (uint32_t)__cvta_generic_to_shared(p);
}
__device__ __forceinline__ void ldsm_x4(uint32_t* r, uint32_t addr) {
    asm volatile("ldmatrix.sync.aligned.m8n8.x4.shared.b16 {%0,%1,%2,%3}, [%4];"
                 : "=r"(r[0]), "=r"(r[1]), "=r"(r[2]), "=r"(r[3]) : "r"(addr));
}
__device__ __forceinline__ void ldsm_x2t(uint32_t* r, uint32_t addr) {
    asm volatile("ldmatrix.sync.aligned.m8n8.x2.trans.shared.b16 {%0,%1}, [%2];"
                 : "=r"(r[0]), "=r"(r[1]) : "r"(addr));
}
__device__ __forceinline__ void mma16816(float* c, const uint32_t* a, const uint32_t* b) {
    asm volatile("mma.sync.aligned.m16n8k16.row.col.f32.f16.f16.f32 "
                 "{%0,%1,%2,%3}, {%4,%5,%6,%7}, {%8,%9}, {%0,%1,%2,%3};"
                 : "+f"(c[0]), "+f"(c[1]), "+f"(c[2]), "+f"(c[3])
                 : "r"(a[0]), "r"(a[1]), "r"(a[2]), "r"(a[3]), "r"(b[0]), "r"(b[1]));
}
__device__ __forceinline__ void cp16(uint32_t saddr, const void* gaddr) {
    asm volatile("cp.async.cg.shared.global [%0], [%1], 16;" :: "r"(saddr), "l"(gaddr));
}
#define CP_COMMIT()  asm volatile("cp.async.commit_group;" ::: "memory")
#define CP_WAIT2()   asm volatile("cp.async.wait_group 2;" ::: "memory")

// ---------------- kernel: init -----------------------------------------------
__global__ void k_init() {
    if (threadIdx.x < NEXP) g_cnt[threadIdx.x] = 0;
}

// ---------------- kernel: fp32 -> fp16 weight convert ------------------------
__global__ void k_cvt(const float* __restrict__ src, __half* __restrict__ dst) {
    int i = blockIdx.x * blockDim.x + threadIdx.x;   // one half8 (16B) unit
    float4 f0 = ((const float4*)src)[2 * i];
    float4 f1 = ((const float4*)src)[2 * i + 1];
    __half2 h[4] = { __floats2half2_rn(f0.x, f0.y), __floats2half2_rn(f0.z, f0.w),
                     __floats2half2_rn(f1.x, f1.y), __floats2half2_rn(f1.z, f1.w) };
    ((uint4*)dst)[i] = *(uint4*)h;
}

// ---------------- kernel: router ----------------------------------------------
__global__ void k_router(const float* __restrict__ x,
                         const float* __restrict__ Wr,
                         const float* __restrict__ br) {
    int t    = blockIdx.x * 8 + (threadIdx.x >> 5);
    int lane = threadIdx.x & 31;
    if (t >= TOKENS) return;

    const float* xr = x + (size_t)t * DDIM;
    float acc[NEXP];
#pragma unroll
    for (int e = 0; e < NEXP; e++) acc[e] = 0.f;

    for (int j = 0; j < DDIM / 32; j++) {
        int d = j * 32 + lane;
        float xv = xr[d];
        g_x16[(size_t)t * DDIM + d] = __float2half_rn(xv);
        const float4* wr4 = (const float4*)(Wr + (size_t)d * NEXP);
        float4 w0 = wr4[0], w1 = wr4[1];
        acc[0] += xv * w0.x; acc[1] += xv * w0.y;
        acc[2] += xv * w0.z; acc[3] += xv * w0.w;
        acc[4] += xv * w1.x; acc[5] += xv * w1.y;
        acc[6] += xv * w1.z; acc[7] += xv * w1.w;
    }
#pragma unroll
    for (int o = 16; o; o >>= 1)
#pragma unroll
        for (int e = 0; e < NEXP; e++)
            acc[e] += __shfl_xor_sync(0xffffffffu, acc[e], o);

    if (lane == 0) {
#pragma unroll
        for (int e = 0; e < NEXP; e++) acc[e] += br[e];
        int i0 = 0;
#pragma unroll
        for (int e = 1; e < NEXP; e++) if (acc[e] > acc[i0]) i0 = e;
        int i1 = -1;
#pragma unroll
        for (int e = 0; e < NEXP; e++) {
            if (e == i0) continue;
            if (i1 < 0 || acc[e] > acc[i1]) i1 = e;
        }
        float ex = expf(acc[i1] - acc[i0]);
        float g0 = 1.f / (1.f + ex);
        float g1 = ex * g0;

        int p0 = atomicAdd(&g_cnt[i0], 1);
        int p1 = atomicAdd(&g_cnt[i1], 1);
        g_idx[i0][p0] = t;
        g_idx[i1][p1] = t;
        g_tok_e[t][0] = i0; g_tok_p[t][0] = p0; g_tok_g[t][0] = g0;
        g_tok_e[t][1] = i1; g_tok_p[t][1] = p1; g_tok_g[t][1] = g1;
    }
}

// ---------------- kernel: offsets ---------------------------------------------
__global__ void k_offsets() {
    if (threadIdx.x == 0) {
        int s = 0;
        for (int e = 0; e < NEXP; e++) { g_off[e] = s; s += g_cnt[e]; }
    }
}

// ---------------- grouped GEMM: CTA 128x256x32, warp 64x64, 4-stage cp.async --
// MODE 0: h[off+m,:] = relu(x16[gather] @ W1h[e] + b1)   (fp16 out to g_h)
// MODE 1: y[off+m,:] = g_h rows @ W2h[e] + b2            (fp32 out to g_y)
#define APADH 40                         // halves per A-smem row (80B)
#define BPADH 264                        // halves per B-smem row (528B)
#define ASZ   (128 * APADH * 2)          // 10240 B
#define BSZ   (32 * BPADH * 2)           // 16896 B
#define STAGE (ASZ + BSZ)                // 27136 B
#define NSTAGE 4

template <int KDIM, int NDIM, int MODE>
__global__ __launch_bounds__(256) void k_gemm(const __half* __restrict__ Wh,
                                              const float* __restrict__ biasg) {
    extern __shared__ __align__(16) char smem[];

    const int e   = blockIdx.z;
    const int cnt = g_cnt[e];
    const int m0  = blockIdx.y * 128;
    if (m0 >= cnt) return;
    const int n0  = blockIdx.x * 256;
    const int off = g_off[e];
    const __half* Wb = Wh + (size_t)e * KDIM * NDIM;

    const int tid  = threadIdx.x;
    const int lane = tid & 31;
    const int warp = tid >> 5;
    const int wm   = warp >> 2;   // 0..1
    const int wn   = warp & 3;    // 0..3

    // ---- A cp.async mapping: thread -> (row = tid&127, two segs)
    const int arow = tid & 127;
    const int aseg = (tid >> 7) * 2;          // seg, seg+1 (16B units of the 64B row-chunk)
    const __half* abase;
    if (MODE == 0) {
        int row = m0 + arow;
        int tok = g_idx[e][row < cnt ? row : (cnt - 1)];
        abase = g_x16 + (size_t)tok * DDIM + aseg * 8;
    } else {
        abase = g_h + (size_t)(off + m0 + arow) * KDIM + aseg * 8;
    }
    const uint32_t as_off = s2u(smem) + (uint32_t)(arow * APADH + aseg * 8) * 2;

    // ---- B cp.async mapping: thread -> (row = tid>>3, 4 gcols gc+8j)
    const int brow = tid >> 3;                // 0..31
    const int bgc  = tid & 7;
    const __half* bbase = Wb + (size_t)brow * NDIM + n0 + bgc * 8;
    const uint32_t bs_off = s2u(smem) + ASZ + (uint32_t)(brow * BPADH + bgc * 8) * 2;

    float acc[4][8][4];
#pragma unroll
    for (int mi = 0; mi < 4; mi++)
#pragma unroll
        for (int ni = 0; ni < 8; ni++)
#pragma unroll
            for (int q = 0; q < 4; q++) acc[mi][ni][q] = 0.f;

    const int NK = KDIM / 32;

    // ---- prologue: stages 0..2
#pragma unroll
    for (int c = 0; c < 3; c++) {
        uint32_t sa = as_off + c * STAGE;
        uint32_t sb = bs_off + c * STAGE;
        cp16(sa,      abase + c * 32);
        cp16(sa + 16, abase + c * 32 + 8);
#pragma unroll
        for (int j = 0; j < 4; j++)
            cp16(sb + j * 128, bbase + (size_t)c * 32 * NDIM + j * 64);
        CP_COMMIT();
    }

    const uint32_t a_rd = s2u(smem) +
        (uint32_t)((wm * 64 + (lane & 15)) * APADH + (lane >> 4) * 8) * 2;
    const uint32_t b_rd = s2u(smem) + ASZ +
        (uint32_t)((lane & 15) * BPADH + wn * 64) * 2;

    for (int kc = 0; kc < NK; kc++) {
        CP_WAIT2();
        __syncthreads();

        // issue stage kc+3 (overwrites stage kc-1's buffer)
        if (kc + 3 < NK) {
            int c = kc + 3, s = c & 3;
            uint32_t sa = as_off + s * STAGE;
            uint32_t sb = bs_off + s * STAGE;
            cp16(sa,      abase + c * 32);
            cp16(sa + 16, abase + c * 32 + 8);
#pragma unroll
            for (int j = 0; j < 4; j++)
                cp16(sb + j * 128, bbase + (size_t)c * 32 * NDIM + j * 64);
        }
        CP_COMMIT();   // empty group when nothing issued keeps the count invariant

        const uint32_t abuf = a_rd + (kc & 3) * STAGE;
        const uint32_t bbuf = b_rd + (kc & 3) * STAGE;
#pragma unroll
        for (int kk = 0; kk < 2; kk++) {
            uint32_t afr[4][4];
            uint32_t bfr[8][2];
#pragma unroll
            for (int mi = 0; mi < 4; mi++)
                ldsm_x4(afr[mi], abuf + (uint32_t)(mi * 16 * APADH + kk * 16) * 2);
#pragma unroll
            for (int ni = 0; ni < 8; ni++)
                ldsm_x2t(bfr[ni], bbuf + (uint32_t)(kk * 16 * BPADH + ni * 8) * 2);
#pragma unroll
            for (int mi = 0; mi < 4; mi++)
#pragma unroll
                for (int ni = 0; ni < 8; ni++)
                    mma16816(acc[mi][ni], afr[mi], bfr[ni]);
        }
        __syncthreads();
    }

    // ---- epilogue
#pragma unroll
    for (int mi = 0; mi < 4; mi++) {
#pragma unroll
        for (int ni = 0; ni < 8; ni++) {
            int r = wm * 64 + mi * 16 + (lane >> 2);
            int c = n0 + wn * 64 + ni * 8 + ((lane & 3) << 1);
            float bv0 = biasg[(size_t)e * NDIM + c];
            float bv1 = biasg[(size_t)e * NDIM + c + 1];
            float v00 = acc[mi][ni][0] + bv0, v01 = acc[mi][ni][1] + bv1;
            float v10 = acc[mi][ni][2] + bv0, v11 = acc[mi][ni][3] + bv1;
            if (MODE == 0) {
                v00 = fmaxf(v00, 0.f); v01 = fmaxf(v01, 0.f);
                v10 = fmaxf(v10, 0.f); v11 = fmaxf(v11, 0.f);
                __half2 p0 = __floats2half2_rn(v00, v01);
                __half2 p1 = __floats2half2_rn(v10, v11);
                if (m0 + r < cnt)
                    *(__half2*)&g_h[(size_t)(off + m0 + r) * NDIM + c] = p0;
                if (m0 + r + 8 < cnt)
                    *(__half2*)&g_h[(size_t)(off + m0 + r + 8) * NDIM + c] = p1;
            } else {
                if (m0 + r < cnt)
                    *(float2*)&g_y[(size_t)(off + m0 + r) * NDIM + c] = make_float2(v00, v01);
                if (m0 + r + 8 < cnt)
                    *(float2*)&g_y[(size_t)(off + m0 + r + 8) * NDIM + c] = make_float2(v10, v11);
            }
        }
    }
}

// ---------------- kernel: combine ---------------------------------------------
__global__ void k_combine(float* __restrict__ out) {
    int t = blockIdx.x;
    int e0 = g_tok_e[t][0], e1 = g_tok_e[t][1];
    int r0 = g_off[e0] + g_tok_p[t][0];
    int r1 = g_off[e1] + g_tok_p[t][1];
    float w0 = g_tok_g[t][0], w1 = g_tok_g[t][1];

    const float4* ya = (const float4*)(g_y + (size_t)r0 * DDIM);
    const float4* yb = (const float4*)(g_y + (size_t)r1 * DDIM);
    float4* o = (float4*)(out + (size_t)t * DDIM);
    int i = threadIdx.x;
    float4 a = ya[i], b = yb[i];
    o[i] = make_float4(w0 * a.x + w1 * b.x,
                       w0 * a.y + w1 * b.y,
                       w0 * a.z + w1 * b.z,
                       w0 * a.w + w1 * b.w);
}

// ---------------- launch ------------------------------------------------------
extern "C" void kernel_launch(void* const* d_in, const int* in_sizes, int n_in,
                              void* d_out, int out_size) {
    const float* x  = (const float*)d_in[0];
    const float* Wr = (const float*)d_in[1];
    const float* br = (const float*)d_in[2];
    const float* W1 = (const float*)d_in[3];
    const float* b1 = (const float*)d_in[4];
    const float* W2 = (const float*)d_in[5];
    const float* b2 = (const float*)d_in[6];
    float* out = (float*)d_out;

    static __half* w1h = nullptr;
    static __half* w2h = nullptr;
    if (!w1h) { cudaGetSymbolAddress((void**)&w1h, g_w1h); }
    if (!w2h) { cudaGetSymbolAddress((void**)&w2h, g_w2h); }

    const int DSMEM = NSTAGE * STAGE;   // 108544
    cudaFuncSetAttribute(k_gemm<DDIM, HDIM, 0>, cudaFuncAttributeMaxDynamicSharedMemorySize, DSMEM);
    cudaFuncSetAttribute(k_gemm<HDIM, DDIM, 1>, cudaFuncAttributeMaxDynamicSharedMemorySize, DSMEM);

    k_init<<<1, 32>>>();
    k_cvt<<<(NEXP * DDIM * HDIM / 8) / 256, 256>>>(W1, w1h);
    k_cvt<<<(NEXP * HDIM * DDIM / 8) / 256, 256>>>(W2, w2h);
    k_router<<<TOKENS / 8, 256>>>(x, Wr, br);
    k_offsets<<<1, 1>>>();

    dim3 g1(HDIM / 256, TOKENS / 128, NEXP);   // (16, 64, 8)
    k_gemm<DDIM, HDIM, 0><<<g1, 256, DSMEM>>>(w1h, b1);

    dim3 g2(DDIM / 256, TOKENS / 128, NEXP);   // (4, 64, 8)
    k_gemm<HDIM, DDIM, 1><<<g2, 256, DSMEM>>>(w2h, b2);

    k_combine<<<TOKENS, 256>>>(out);
}

// round 7
// speedup vs baseline: 1.0618x; 1.0618x over previous
#include <cuda_runtime.h>
#include <cuda_fp16.h>
#include <cstdint>
#include <math.h>

#define TOKENS 8192
#define DDIM   1024
#define HDIM   4096
#define NEXP   8
#define TOTROWS (2*TOKENS)

// ---------------- device scratch ---------------------------------------------
__device__ __half g_x16[(size_t)TOKENS * DDIM];
__device__ __half g_w1h[(size_t)NEXP * DDIM * HDIM];     // W1 fp16 [E,K,N]
__device__ __half g_w2h[(size_t)NEXP * HDIM * DDIM];     // W2 fp16 [E,K,N]
__device__ __half g_h[(size_t)(TOTROWS + 128) * HDIM];
__device__ float  g_y[(size_t)TOTROWS * DDIM];
__device__ int    g_cnt[NEXP];
__device__ int    g_off[NEXP];
__device__ int    g_idx[NEXP][TOKENS];
__device__ int    g_tok_e[TOKENS][2];
__device__ int    g_tok_p[TOKENS][2];
__device__ float  g_tok_g[TOKENS][2];

// ---------------- helpers ----------------------------------------------------
__device__ __forceinline__ uint32_t s2u(const void* p) {
    return (uint32_t)__cvta_generic_to_shared(p);
}
__device__ __forceinline__ void ldsm_x4(uint32_t* r, uint32_t addr) {
    asm volatile("ldmatrix.sync.aligned.m8n8.x4.shared.b16 {%0,%1,%2,%3}, [%4];"
                 : "=r"(r[0]), "=r"(r[1]), "=r"(r[2]), "=r"(r[3]) : "r"(addr));
}
__device__ __forceinline__ void ldsm_x2t(uint32_t* r, uint32_t addr) {
    asm volatile("ldmatrix.sync.aligned.m8n8.x2.trans.shared.b16 {%0,%1}, [%2];"
                 : "=r"(r[0]), "=r"(r[1]) : "r"(addr));
}
__device__ __forceinline__ void mma16816(float* c, const uint32_t* a, const uint32_t* b) {
    asm volatile("mma.sync.aligned.m16n8k16.row.col.f32.f16.f16.f32 "
                 "{%0,%1,%2,%3}, {%4,%5,%6,%7}, {%8,%9}, {%0,%1,%2,%3};"
                 : "+f"(c[0]), "+f"(c[1]), "+f"(c[2]), "+f"(c[3])
                 : "r"(a[0]), "r"(a[1]), "r"(a[2]), "r"(a[3]), "r"(b[0]), "r"(b[1]));
}
__device__ __forceinline__ void cp16(uint32_t saddr, const void* gaddr) {
    asm volatile("cp.async.cg.shared.global [%0], [%1], 16;" :: "r"(saddr), "l"(gaddr));
}
#define CP_COMMIT()  asm volatile("cp.async.commit_group;" ::: "memory")
#define CP_WAIT1()   asm volatile("cp.async.wait_group 1;" ::: "memory")

// ---------------- kernel: init -----------------------------------------------
__global__ void k_init() {
    if (threadIdx.x < NEXP) g_cnt[threadIdx.x] = 0;
}

// ---------------- kernel: fp32 -> fp16 weight convert ------------------------
__global__ void k_cvt(const float* __restrict__ src, __half* __restrict__ dst) {
    int i = blockIdx.x * blockDim.x + threadIdx.x;   // one half8 (16B) unit
    float4 f0 = ((const float4*)src)[2 * i];
    float4 f1 = ((const float4*)src)[2 * i + 1];
    __half2 h[4] = { __floats2half2_rn(f0.x, f0.y), __floats2half2_rn(f0.z, f0.w),
                     __floats2half2_rn(f1.x, f1.y), __floats2half2_rn(f1.z, f1.w) };
    ((uint4*)dst)[i] = *(uint4*)h;
}

// ---------------- kernel: router ----------------------------------------------
__global__ void k_router(const float* __restrict__ x,
                         const float* __restrict__ Wr,
                         const float* __restrict__ br) {
    int t    = blockIdx.x * 8 + (threadIdx.x >> 5);
    int lane = threadIdx.x & 31;
    if (t >= TOKENS) return;

    const float* xr = x + (size_t)t * DDIM;
    float acc[NEXP];
#pragma unroll
    for (int e = 0; e < NEXP; e++) acc[e] = 0.f;

    for (int j = 0; j < DDIM / 32; j++) {
        int d = j * 32 + lane;
        float xv = xr[d];
        g_x16[(size_t)t * DDIM + d] = __float2half_rn(xv);
        const float4* wr4 = (const float4*)(Wr + (size_t)d * NEXP);
        float4 w0 = wr4[0], w1 = wr4[1];
        acc[0] += xv * w0.x; acc[1] += xv * w0.y;
        acc[2] += xv * w0.z; acc[3] += xv * w0.w;
        acc[4] += xv * w1.x; acc[5] += xv * w1.y;
        acc[6] += xv * w1.z; acc[7] += xv * w1.w;
    }
#pragma unroll
    for (int o = 16; o; o >>= 1)
#pragma unroll
        for (int e = 0; e < NEXP; e++)
            acc[e] += __shfl_xor_sync(0xffffffffu, acc[e], o);

    if (lane == 0) {
#pragma unroll
        for (int e = 0; e < NEXP; e++) acc[e] += br[e];
        int i0 = 0;
#pragma unroll
        for (int e = 1; e < NEXP; e++) if (acc[e] > acc[i0]) i0 = e;
        int i1 = -1;
#pragma unroll
        for (int e = 0; e < NEXP; e++) {
            if (e == i0) continue;
            if (i1 < 0 || acc[e] > acc[i1]) i1 = e;
        }
        float ex = expf(acc[i1] - acc[i0]);
        float g0 = 1.f / (1.f + ex);
        float g1 = ex * g0;

        int p0 = atomicAdd(&g_cnt[i0], 1);
        int p1 = atomicAdd(&g_cnt[i1], 1);
        g_idx[i0][p0] = t;
        g_idx[i1][p1] = t;
        g_tok_e[t][0] = i0; g_tok_p[t][0] = p0; g_tok_g[t][0] = g0;
        g_tok_e[t][1] = i1; g_tok_p[t][1] = p1; g_tok_g[t][1] = g1;
    }
}

// ---------------- kernel: offsets ---------------------------------------------
__global__ void k_offsets() {
    if (threadIdx.x == 0) {
        int s = 0;
        for (int e = 0; e < NEXP; e++) { g_off[e] = s; s += g_cnt[e]; }
    }
}

// ---- grouped GEMM: CTA 128x256x32, 512 thr, 16 warps (4m x 4n), warp 32x64 ---
// MODE 0: h[off+m,:] = relu(x16[gather] @ W1h[e] + b1)   (fp16 out to g_h)
// MODE 1: y[off+m,:] = g_h rows @ W2h[e] + b2            (fp32 out to g_y)
#define APADH 40                         // halves per A-smem row (80B)
#define BPADH 264                        // halves per B-smem row (528B)
#define ASZ   (128 * APADH * 2)          // 10240 B
#define BSZ   (32 * BPADH * 2)           // 16896 B
#define STAGE (ASZ + BSZ)                // 27136 B
#define NSTAGE 3

template <int KDIM, int NDIM, int MODE>
__global__ __launch_bounds__(512, 1) void k_gemm(const __half* __restrict__ Wh,
                                                 const float* __restrict__ biasg) {
    extern __shared__ __align__(16) char smem[];

    const int e   = blockIdx.z;
    const int cnt = g_cnt[e];
    const int m0  = blockIdx.y * 128;
    if (m0 >= cnt) return;
    const int n0  = blockIdx.x * 256;
    const int off = g_off[e];
    const __half* Wb = Wh + (size_t)e * KDIM * NDIM;

    const int tid  = threadIdx.x;
    const int lane = tid & 31;
    const int warp = tid >> 5;
    const int wm   = warp >> 2;   // 0..3  (m-quadrant, 32 rows each)
    const int wn   = warp & 3;    // 0..3  (n-quadrant, 64 cols each)

    // ---- A cp.async: 512 threads cover 128 rows x 4 segs of 16B (one each)
    const int arow = tid >> 2;
    const int aseg = tid & 3;
    const __half* abase;
    if (MODE == 0) {
        int row = m0 + arow;
        int tok = g_idx[e][row < cnt ? row : (cnt - 1)];
        abase = g_x16 + (size_t)tok * DDIM + aseg * 8;
    } else {
        abase = g_h + (size_t)(off + m0 + arow) * KDIM + aseg * 8;
    }
    const uint32_t as_off = s2u(smem) + (uint32_t)(arow * APADH + aseg * 8) * 2;

    // ---- B cp.async: 1024 units of 16B -> 2 per thread; warp = one 512B row span
    const int brow0 = tid >> 5;           // 0..15
    const int bc16  = tid & 31;           // 16B col unit
    const __half* bbase = Wb + (size_t)brow0 * NDIM + n0 + bc16 * 8;
    const uint32_t bs_off = s2u(smem) + ASZ + (uint32_t)(brow0 * BPADH + bc16 * 8) * 2;

    float acc[2][8][4];
#pragma unroll
    for (int mi = 0; mi < 2; mi++)
#pragma unroll
        for (int ni = 0; ni < 8; ni++)
#pragma unroll
            for (int q = 0; q < 4; q++) acc[mi][ni][q] = 0.f;

    const int NK = KDIM / 32;

    // ---- prologue: stages 0..1
#pragma unroll
    for (int c = 0; c < 2; c++) {
        cp16(as_off + c * STAGE, abase + c * 32);
        cp16(bs_off + c * STAGE,                      bbase + (size_t)c * 32 * NDIM);
        cp16(bs_off + c * STAGE + 16 * BPADH * 2,     bbase + (size_t)(c * 32 + 16) * NDIM);
        CP_COMMIT();
    }

    const uint32_t a_rd = s2u(smem) +
        (uint32_t)((wm * 32 + (lane & 15)) * APADH + (lane >> 4) * 8) * 2;
    const uint32_t b_rd = s2u(smem) + ASZ +
        (uint32_t)((lane & 15) * BPADH + wn * 64) * 2;

    for (int kc = 0; kc < NK; kc++) {
        CP_WAIT1();
        __syncthreads();

        // prefetch stage kc+2 (buffer (kc+2)%3; its old contents finished at kc-1)
        if (kc + 2 < NK) {
            int c = kc + 2, s = c % NSTAGE;
            cp16(as_off + s * STAGE, abase + c * 32);
            cp16(bs_off + s * STAGE,                  bbase + (size_t)c * 32 * NDIM);
            cp16(bs_off + s * STAGE + 16 * BPADH * 2, bbase + (size_t)(c * 32 + 16) * NDIM);
        }
        CP_COMMIT();

        const uint32_t abuf = a_rd + (kc % NSTAGE) * STAGE;
        const uint32_t bbuf = b_rd + (kc % NSTAGE) * STAGE;
#pragma unroll
        for (int kk = 0; kk < 2; kk++) {
            uint32_t afr[2][4];
            uint32_t bfr[8][2];
#pragma unroll
            for (int mi = 0; mi < 2; mi++)
                ldsm_x4(afr[mi], abuf + (uint32_t)(mi * 16 * APADH + kk * 16) * 2);
#pragma unroll
            for (int ni = 0; ni < 8; ni++)
                ldsm_x2t(bfr[ni], bbuf + (uint32_t)(kk * 16 * BPADH + ni * 8) * 2);
#pragma unroll
            for (int mi = 0; mi < 2; mi++)
#pragma unroll
                for (int ni = 0; ni < 8; ni++)
                    mma16816(acc[mi][ni], afr[mi], bfr[ni]);
        }
        __syncthreads();
    }

    // ---- epilogue
#pragma unroll
    for (int mi = 0; mi < 2; mi++) {
#pragma unroll
        for (int ni = 0; ni < 8; ni++) {
            int r = wm * 32 + mi * 16 + (lane >> 2);
            int c = n0 + wn * 64 + ni * 8 + ((lane & 3) << 1);
            float bv0 = biasg[(size_t)e * NDIM + c];
            float bv1 = biasg[(size_t)e * NDIM + c + 1];
            float v00 = acc[mi][ni][0] + bv0, v01 = acc[mi][ni][1] + bv1;
            float v10 = acc[mi][ni][2] + bv0, v11 = acc[mi][ni][3] + bv1;
            if (MODE == 0) {
                v00 = fmaxf(v00, 0.f); v01 = fmaxf(v01, 0.f);
                v10 = fmaxf(v10, 0.f); v11 = fmaxf(v11, 0.f);
                __half2 p0 = __floats2half2_rn(v00, v01);
                __half2 p1 = __floats2half2_rn(v10, v11);
                if (m0 + r < cnt)
                    *(__half2*)&g_h[(size_t)(off + m0 + r) * NDIM + c] = p0;
                if (m0 + r + 8 < cnt)
                    *(__half2*)&g_h[(size_t)(off + m0 + r + 8) * NDIM + c] = p1;
            } else {
                if (m0 + r < cnt)
                    *(float2*)&g_y[(size_t)(off + m0 + r) * NDIM + c] = make_float2(v00, v01);
                if (m0 + r + 8 < cnt)
                    *(float2*)&g_y[(size_t)(off + m0 + r + 8) * NDIM + c] = make_float2(v10, v11);
            }
        }
    }
}

// ---------------- kernel: combine ---------------------------------------------
__global__ void k_combine(float* __restrict__ out) {
    int t = blockIdx.x;
    int e0 = g_tok_e[t][0], e1 = g_tok_e[t][1];
    int r0 = g_off[e0] + g_tok_p[t][0];
    int r1 = g_off[e1] + g_tok_p[t][1];
    float w0 = g_tok_g[t][0], w1 = g_tok_g[t][1];

    const float4* ya = (const float4*)(g_y + (size_t)r0 * DDIM);
    const float4* yb = (const float4*)(g_y + (size_t)r1 * DDIM);
    float4* o = (float4*)(out + (size_t)t * DDIM);
    int i = threadIdx.x;
    float4 a = ya[i], b = yb[i];
    o[i] = make_float4(w0 * a.x + w1 * b.x,
                       w0 * a.y + w1 * b.y,
                       w0 * a.z + w1 * b.z,
                       w0 * a.w + w1 * b.w);
}

// ---------------- launch ------------------------------------------------------
extern "C" void kernel_launch(void* const* d_in, const int* in_sizes, int n_in,
                              void* d_out, int out_size) {
    const float* x  = (const float*)d_in[0];
    const float* Wr = (const float*)d_in[1];
    const float* br = (const float*)d_in[2];
    const float* W1 = (const float*)d_in[3];
    const float* b1 = (const float*)d_in[4];
    const float* W2 = (const float*)d_in[5];
    const float* b2 = (const float*)d_in[6];
    float* out = (float*)d_out;

    static __half* w1h = nullptr;
    static __half* w2h = nullptr;
    if (!w1h) { cudaGetSymbolAddress((void**)&w1h, g_w1h); }
    if (!w2h) { cudaGetSymbolAddress((void**)&w2h, g_w2h); }

    const int DSMEM = NSTAGE * STAGE;   // 81408
    cudaFuncSetAttribute(k_gemm<DDIM, HDIM, 0>, cudaFuncAttributeMaxDynamicSharedMemorySize, DSMEM);
    cudaFuncSetAttribute(k_gemm<HDIM, DDIM, 1>, cudaFuncAttributeMaxDynamicSharedMemorySize, DSMEM);

    k_init<<<1, 32>>>();
    k_cvt<<<(NEXP * DDIM * HDIM / 8) / 256, 256>>>(W1, w1h);
    k_cvt<<<(NEXP * HDIM * DDIM / 8) / 256, 256>>>(W2, w2h);
    k_router<<<TOKENS / 8, 256>>>(x, Wr, br);
    k_offsets<<<1, 1>>>();

    dim3 g1(HDIM / 256, TOKENS / 128, NEXP);   // (16, 64, 8)
    k_gemm<DDIM, HDIM, 0><<<g1, 512, DSMEM>>>(w1h, b1);

    dim3 g2(DDIM / 256, TOKENS / 128, NEXP);   // (4, 64, 8)
    k_gemm<HDIM, DDIM, 1><<<g2, 512, DSMEM>>>(w2h, b2);

    k_combine<<<TOKENS, 256>>>(out);
}

// round 9
// speedup vs baseline: 1.1813x; 1.1125x over previous
#include <cuda_runtime.h>
#include <cuda_fp16.h>
#include <cstdint>
#include <math.h>

#define TOKENS 8192
#define DDIM   1024
#define HDIM   4096
#define NEXP   8
#define TOTROWS (2*TOKENS)

// ---------------- device scratch ---------------------------------------------
__device__ __half g_x16[(size_t)TOKENS * DDIM];
__device__ __half g_w1h[(size_t)NEXP * DDIM * HDIM];     // W1 fp16 [E,K,N]
__device__ __half g_w2h[(size_t)NEXP * HDIM * DDIM];     // W2 fp16 [E,K,N]
__device__ __half g_h[(size_t)(TOTROWS + 128) * HDIM];
__device__ float  g_y[(size_t)TOTROWS * DDIM];
__device__ int    g_cnt[NEXP];
__device__ int    g_off[NEXP];
__device__ int    g_idx[NEXP][TOKENS];
__device__ int    g_tok_e[TOKENS][2];
__device__ int    g_tok_p[TOKENS][2];
__device__ float  g_tok_g[TOKENS][2];

// ---------------- helpers ----------------------------------------------------
__device__ __forceinline__ uint32_t s2u(const void* p) {
    return (uint32_t)__cvta_generic_to_shared(p);
}
__device__ __forceinline__ void ldsm_x4(uint32_t* r, uint32_t addr) {
    asm volatile("ldmatrix.sync.aligned.m8n8.x4.shared.b16 {%0,%1,%2,%3}, [%4];"
                 : "=r"(r[0]), "=r"(r[1]), "=r"(r[2]), "=r"(r[3]) : "r"(addr));
}
__device__ __forceinline__ void ldsm_x4t(uint32_t* r, uint32_t addr) {
    asm volatile("ldmatrix.sync.aligned.m8n8.x4.trans.shared.b16 {%0,%1,%2,%3}, [%4];"
                 : "=r"(r[0]), "=r"(r[1]), "=r"(r[2]), "=r"(r[3]) : "r"(addr));
}
__device__ __forceinline__ void mma16816(float* c, const uint32_t* a, const uint32_t* b) {
    asm volatile("mma.sync.aligned.m16n8k16.row.col.f32.f16.f16.f32 "
                 "{%0,%1,%2,%3}, {%4,%5,%6,%7}, {%8,%9}, {%0,%1,%2,%3};"
                 : "+f"(c[0]), "+f"(c[1]), "+f"(c[2]), "+f"(c[3])
                 : "r"(a[0]), "r"(a[1]), "r"(a[2]), "r"(a[3]), "r"(b[0]), "r"(b[1]));
}
__device__ __forceinline__ void cp16(uint32_t saddr, const void* gaddr) {
    asm volatile("cp.async.cg.shared.global [%0], [%1], 16;" :: "r"(saddr), "l"(gaddr));
}
#define CP_COMMIT()  asm volatile("cp.async.commit_group;" ::: "memory")
#define CP_WAIT1()   asm volatile("cp.async.wait_group 1;" ::: "memory")

// ---------------- kernel: init -----------------------------------------------
__global__ void k_init() {
    if (threadIdx.x < NEXP) g_cnt[threadIdx.x] = 0;
}

// ---------------- kernel: fp32 -> fp16 weight convert ------------------------
__global__ void k_cvt(const float* __restrict__ src, __half* __restrict__ dst) {
    int i = blockIdx.x * blockDim.x + threadIdx.x;   // one half8 (16B) unit
    float4 f0 = ((const float4*)src)[2 * i];
    float4 f1 = ((const float4*)src)[2 * i + 1];
    __half2 h[4] = { __floats2half2_rn(f0.x, f0.y), __floats2half2_rn(f0.z, f0.w),
                     __floats2half2_rn(f1.x, f1.y), __floats2half2_rn(f1.z, f1.w) };
    ((uint4*)dst)[i] = *(uint4*)h;
}

// ---------------- kernel: router ----------------------------------------------
__global__ void k_router(const float* __restrict__ x,
                         const float* __restrict__ Wr,
                         const float* __restrict__ br) {
    int t    = blockIdx.x * 8 + (threadIdx.x >> 5);
    int lane = threadIdx.x & 31;
    if (t >= TOKENS) return;

    const float* xr = x + (size_t)t * DDIM;
    float acc[NEXP];
#pragma unroll
    for (int e = 0; e < NEXP; e++) acc[e] = 0.f;

    for (int j = 0; j < DDIM / 32; j++) {
        int d = j * 32 + lane;
        float xv = xr[d];
        g_x16[(size_t)t * DDIM + d] = __float2half_rn(xv);
        const float4* wr4 = (const float4*)(Wr + (size_t)d * NEXP);
        float4 w0 = wr4[0], w1 = wr4[1];
        acc[0] += xv * w0.x; acc[1] += xv * w0.y;
        acc[2] += xv * w0.z; acc[3] += xv * w0.w;
        acc[4] += xv * w1.x; acc[5] += xv * w1.y;
        acc[6] += xv * w1.z; acc[7] += xv * w1.w;
    }
#pragma unroll
    for (int o = 16; o; o >>= 1)
#pragma unroll
        for (int e = 0; e < NEXP; e++)
            acc[e] += __shfl_xor_sync(0xffffffffu, acc[e], o);

    if (lane == 0) {
#pragma unroll
        for (int e = 0; e < NEXP; e++) acc[e] += br[e];
        int i0 = 0;
#pragma unroll
        for (int e = 1; e < NEXP; e++) if (acc[e] > acc[i0]) i0 = e;
        int i1 = -1;
#pragma unroll
        for (int e = 0; e < NEXP; e++) {
            if (e == i0) continue;
            if (i1 < 0 || acc[e] > acc[i1]) i1 = e;
        }
        float ex = expf(acc[i1] - acc[i0]);
        float g0 = 1.f / (1.f + ex);
        float g1 = ex * g0;

        int p0 = atomicAdd(&g_cnt[i0], 1);
        int p1 = atomicAdd(&g_cnt[i1], 1);
        g_idx[i0][p0] = t;
        g_idx[i1][p1] = t;
        g_tok_e[t][0] = i0; g_tok_p[t][0] = p0; g_tok_g[t][0] = g0;
        g_tok_e[t][1] = i1; g_tok_p[t][1] = p1; g_tok_g[t][1] = g1;
    }
}

// ---------------- kernel: offsets ---------------------------------------------
__global__ void k_offsets() {
    if (threadIdx.x == 0) {
        int s = 0;
        for (int e = 0; e < NEXP; e++) { g_off[e] = s; s += g_cnt[e]; }
    }
}

// ---- grouped GEMM: CTA 128x256x64, 512 thr, 16 warps (4m x 4n), warp 32x64 ---
// MODE 0: h[off+m,:] = relu(x16[gather] @ W1h[e] + b1)   (fp16 out to g_h)
// MODE 1: y[off+m,:] = g_h rows @ W2h[e] + b2            (fp32 out to g_y)
#define APADH 72                         // halves per A-smem row (144B)
#define BPADH 264                        // halves per B-smem row (528B)
#define ASZ   (128 * APADH * 2)          // 18432 B
#define BSZ   (64 * BPADH * 2)           // 33792 B
#define STAGE (ASZ + BSZ)                // 52224 B
#define NSTAGE 3

template <int KDIM, int NDIM, int MODE>
__global__ __launch_bounds__(512, 1) void k_gemm(const __half* __restrict__ Wh,
                                                 const float* __restrict__ biasg) {
    extern __shared__ __align__(16) char smem[];

    const int e   = blockIdx.z;
    const int cnt = g_cnt[e];
    const int m0  = blockIdx.y * 128;
    if (m0 >= cnt) return;
    const int n0  = blockIdx.x * 256;
    const int off = g_off[e];
    const __half* Wb = Wh + (size_t)e * KDIM * NDIM;

    const int tid  = threadIdx.x;
    const int lane = tid & 31;
    const int warp = tid >> 5;
    const int wm   = warp >> 2;   // 0..3  (m-quadrant, 32 rows)
    const int wn   = warp & 3;    // 0..3  (n-quadrant, 64 cols)

    // ---- A cp.async: 128 rows x 8 x 16B units -> 2 cp16 per thread
    const int arow  = tid >> 2;
    const int aunit = (tid & 3) * 2;          // 16B units {0,2,4,6}
    const __half* abase;
    if (MODE == 0) {
        int row = m0 + arow;
        int tok = g_idx[e][row < cnt ? row : (cnt - 1)];
        abase = g_x16 + (size_t)tok * DDIM + aunit * 8;
    } else {
        abase = g_h + (size_t)(off + m0 + arow) * KDIM + aunit * 8;
    }
    const uint32_t as_off = s2u(smem) + (uint32_t)(arow * APADH + aunit * 8) * 2;

    // ---- B cp.async: 64 rows x 32 x 16B units -> 4 cp16 per thread
    //      unit u = bu0 + 8j  ->  smem byte offset (brow*BPADH + u*8)*2 = base + j*128
    const int brow = tid >> 3;                // 0..63
    const int bu0  = tid & 7;                 // unit within row, +8j
    const __half* bbase = Wb + (size_t)brow * NDIM + n0 + bu0 * 8;
    const uint32_t bs_off = s2u(smem) + ASZ + (uint32_t)(brow * BPADH + bu0 * 8) * 2;

    float acc[2][8][4];
#pragma unroll
    for (int mi = 0; mi < 2; mi++)
#pragma unroll
        for (int ni = 0; ni < 8; ni++)
#pragma unroll
            for (int q = 0; q < 4; q++) acc[mi][ni][q] = 0.f;

    const int NK = KDIM / 64;

    // ---- prologue: stages 0..1
#pragma unroll
    for (int c = 0; c < 2; c++) {
        uint32_t sa = as_off + c * STAGE;
        uint32_t sb = bs_off + c * STAGE;
        cp16(sa,      abase + (size_t)c * 64);
        cp16(sa + 16, abase + (size_t)c * 64 + 8);
#pragma unroll
        for (int j = 0; j < 4; j++)
            cp16(sb + j * 128, bbase + (size_t)c * 64 * NDIM + j * 64);
        CP_COMMIT();
    }

    const uint32_t a_rd = s2u(smem) +
        (uint32_t)((wm * 32 + (lane & 15)) * APADH + (lane >> 4) * 8) * 2;
    const uint32_t b_rd = s2u(smem) + ASZ +
        (uint32_t)((lane & 15) * BPADH + wn * 64 + (lane >> 4) * 8) * 2;

    for (int kc = 0; kc < NK; kc++) {
        CP_WAIT1();
        __syncthreads();   // stage kc visible; stage (kc+2)%3 fully consumed (iter kc-1)

        if (kc + 2 < NK) {
            int c = kc + 2, s = c % NSTAGE;
            uint32_t sa = as_off + s * STAGE;
            uint32_t sb = bs_off + s * STAGE;
            cp16(sa,      abase + (size_t)c * 64);
            cp16(sa + 16, abase + (size_t)c * 64 + 8);
#pragma unroll
            for (int j = 0; j < 4; j++)
                cp16(sb + j * 128, bbase + (size_t)c * 64 * NDIM + j * 64);
        }
        CP_COMMIT();

        const uint32_t abuf = a_rd + (kc % NSTAGE) * STAGE;
        const uint32_t bbuf = b_rd + (kc % NSTAGE) * STAGE;
#pragma unroll
        for (int kk = 0; kk < 4; kk++) {
            uint32_t afr[2][4];
            uint32_t bfr[4][4];
#pragma unroll
            for (int mi = 0; mi < 2; mi++)
                ldsm_x4(afr[mi], abuf + (uint32_t)(mi * 16 * APADH + kk * 16) * 2);
#pragma unroll
            for (int j = 0; j < 4; j++)
                ldsm_x4t(bfr[j], bbuf + (uint32_t)(kk * 16 * BPADH + j * 16) * 2);
#pragma unroll
            for (int mi = 0; mi < 2; mi++)
#pragma unroll
                for (int j = 0; j < 4; j++) {
                    mma16816(acc[mi][2 * j],     afr[mi], &bfr[j][0]);
                    mma16816(acc[mi][2 * j + 1], afr[mi], &bfr[j][2]);
                }
        }
    }

    // ---- epilogue
#pragma unroll
    for (int mi = 0; mi < 2; mi++) {
#pragma unroll
        for (int ni = 0; ni < 8; ni++) {
            int r = wm * 32 + mi * 16 + (lane >> 2);
            int c = n0 + wn * 64 + ni * 8 + ((lane & 3) << 1);
            float bv0 = biasg[(size_t)e * NDIM + c];
            float bv1 = biasg[(size_t)e * NDIM + c + 1];
            float v00 = acc[mi][ni][0] + bv0, v01 = acc[mi][ni][1] + bv1;
            float v10 = acc[mi][ni][2] + bv0, v11 = acc[mi][ni][3] + bv1;
            if (MODE == 0) {
                v00 = fmaxf(v00, 0.f); v01 = fmaxf(v01, 0.f);
                v10 = fmaxf(v10, 0.f); v11 = fmaxf(v11, 0.f);
                __half2 p0 = __floats2half2_rn(v00, v01);
                __half2 p1 = __floats2half2_rn(v10, v11);
                if (m0 + r < cnt)
                    *(__half2*)&g_h[(size_t)(off + m0 + r) * NDIM + c] = p0;
                if (m0 + r + 8 < cnt)
                    *(__half2*)&g_h[(size_t)(off + m0 + r + 8) * NDIM + c] = p1;
            } else {
                if (m0 + r < cnt)
                    *(float2*)&g_y[(size_t)(off + m0 + r) * NDIM + c] = make_float2(v00, v01);
                if (m0 + r + 8 < cnt)
                    *(float2*)&g_y[(size_t)(off + m0 + r + 8) * NDIM + c] = make_float2(v10, v11);
            }
        }
    }
}

// ---------------- kernel: combine ---------------------------------------------
__global__ void k_combine(float* __restrict__ out) {
    int t = blockIdx.x;
    int e0 = g_tok_e[t][0], e1 = g_tok_e[t][1];
    int r0 = g_off[e0] + g_tok_p[t][0];
    int r1 = g_off[e1] + g_tok_p[t][1];
    float w0 = g_tok_g[t][0], w1 = g_tok_g[t][1];

    const float4* ya = (const float4*)(g_y + (size_t)r0 * DDIM);
    const float4* yb = (const float4*)(g_y + (size_t)r1 * DDIM);
    float4* o = (float4*)(out + (size_t)t * DDIM);
    int i = threadIdx.x;
    float4 a = ya[i], b = yb[i];
    o[i] = make_float4(w0 * a.x + w1 * b.x,
                       w0 * a.y + w1 * b.y,
                       w0 * a.z + w1 * b.z,
                       w0 * a.w + w1 * b.w);
}

// ---------------- launch ------------------------------------------------------
extern "C" void kernel_launch(void* const* d_in, const int* in_sizes, int n_in,
                              void* d_out, int out_size) {
    const float* x  = (const float*)d_in[0];
    const float* Wr = (const float*)d_in[1];
    const float* br = (const float*)d_in[2];
    const float* W1 = (const float*)d_in[3];
    const float* b1 = (const float*)d_in[4];
    const float* W2 = (const float*)d_in[5];
    const float* b2 = (const float*)d_in[6];
    float* out = (float*)d_out;

    static __half* w1h = nullptr;
    static __half* w2h = nullptr;
    if (!w1h) { cudaGetSymbolAddress((void**)&w1h, g_w1h); }
    if (!w2h) { cudaGetSymbolAddress((void**)&w2h, g_w2h); }

    const int DSMEM = NSTAGE * STAGE;   // 156672
    cudaFuncSetAttribute(k_gemm<DDIM, HDIM, 0>, cudaFuncAttributeMaxDynamicSharedMemorySize, DSMEM);
    cudaFuncSetAttribute(k_gemm<HDIM, DDIM, 1>, cudaFuncAttributeMaxDynamicSharedMemorySize, DSMEM);

    k_init<<<1, 32>>>();
    k_cvt<<<(NEXP * DDIM * HDIM / 8) / 256, 256>>>(W1, w1h);
    k_cvt<<<(NEXP * HDIM * DDIM / 8) / 256, 256>>>(W2, w2h);
    k_router<<<TOKENS / 8, 256>>>(x, Wr, br);
    k_offsets<<<1, 1>>>();

    dim3 g1(HDIM / 256, TOKENS / 128, NEXP);   // (16, 64, 8)
    k_gemm<DDIM, HDIM, 0><<<g1, 512, DSMEM>>>(w1h, b1);

    dim3 g2(DDIM / 256, TOKENS / 128, NEXP);   // (4, 64, 8)
    k_gemm<HDIM, DDIM, 1><<<g2, 512, DSMEM>>>(w2h, b2);

    k_combine<<<TOKENS, 256>>>(out);
}